// round 3
// baseline (speedup 1.0000x reference)
#include <cuda_runtime.h>
#include <cstdint>

#define N_NODES 100000
#define N_EDGES 1600000
#define N_GRAPHS 512

// ---------------- scratch (device globals; no allocation allowed) ----------
__device__ int                g_degi[N_NODES];     // edge count per dst
__device__ int                g_off[N_NODES];      // CSR exclusive offsets
__device__ int                g_cursor[N_NODES];   // fill cursor -> becomes CSR end
__device__ unsigned long long g_csr[N_EDGES];      // packed (src, norm)
__device__ float              g_h1[N_NODES * 32];
__device__ float              g_out1[N_NODES * 32];
__device__ float              g_h2[N_NODES * 32];
__device__ float              g_gsum[N_GRAPHS];
__device__ float              g_gcnt[N_GRAPHS];
__device__ int                g_is64;

// ---------------- f32x2 helpers (Blackwell packed FFMA) ---------------------
__device__ __forceinline__ unsigned long long pack2(float x) {
    unsigned long long r;
    asm("mov.b64 %0, {%1, %1};" : "=l"(r) : "r"(__float_as_uint(x)));
    return r;
}
__device__ __forceinline__ void ffma2(unsigned long long& d,
                                      unsigned long long a,
                                      unsigned long long b) {
    asm("fma.rn.f32x2 %0, %1, %2, %0;" : "+l"(d) : "l"(a), "l"(b));
}

// ---------------- dtype detection ------------------------------------------
__global__ void detect_kernel(const void* ei) {
    __shared__ int bad;
    if (threadIdx.x == 0) bad = 0;
    __syncthreads();
    const unsigned long long* p = (const unsigned long long*)ei;
    for (int i = threadIdx.x; i < 1024; i += 256)
        if (p[i] >= (unsigned long long)N_NODES) bad = 1;
    __syncthreads();
    if (threadIdx.x == 0) g_is64 = bad ? 0 : 1;
}

// ---------------- degree histogram (dst only) -------------------------------
__global__ void deg_kernel(const void* ei) {
    int e = blockIdx.x * 256 + threadIdx.x;
    if (e >= N_EDGES) return;
    int d;
    if (g_is64) d = (int)((const long long*)ei)[N_EDGES + e];
    else        d = ((const int*)ei)[N_EDGES + e];
    d = min(max(d, 0), N_NODES - 1);
    atomicAdd(&g_degi[d], 1);
}

// ---------------- single-block exclusive scan over 100K degrees -------------
__global__ void scan_kernel() {
    const int T = 1024;
    const int IT = (N_NODES + T - 1) / T;   // 98
    int t = threadIdx.x;
    int base = t * IT;
    // pass 1: per-thread sum
    int s = 0;
    for (int i = 0; i < IT; i++) {
        int idx = base + i;
        if (idx < N_NODES) s += g_degi[idx];
    }
    // block-wide exclusive scan (Hillis-Steele)
    __shared__ int sm[T];
    sm[t] = s;
    __syncthreads();
    for (int off = 1; off < T; off <<= 1) {
        int v = (t >= off) ? sm[t - off] : 0;
        __syncthreads();
        sm[t] += v;
        __syncthreads();
    }
    int run = sm[t] - s;   // exclusive prefix of this thread's chunk
    // pass 2: write per-element exclusive offsets + cursors
    for (int i = 0; i < IT; i++) {
        int idx = base + i;
        if (idx < N_NODES) {
            int dv = g_degi[idx];
            g_off[idx] = run;
            g_cursor[idx] = run;
            run += dv;
        }
    }
}

// ---------------- CSR fill: counting-sort edges by dst ----------------------
__global__ void fill_kernel(const void* ei) {
    int e = blockIdx.x * 256 + threadIdx.x;
    if (e >= N_EDGES) return;
    int s, d;
    if (g_is64) {
        const long long* p = (const long long*)ei;
        s = (int)p[e]; d = (int)p[N_EDGES + e];
    } else {
        const int* p = (const int*)ei;
        s = p[e]; d = p[N_EDGES + e];
    }
    s = min(max(s, 0), N_NODES - 1);
    d = min(max(d, 0), N_NODES - 1);
    float ns = rsqrtf((float)g_degi[s] + 1.0f);
    float nd = rsqrtf((float)g_degi[d] + 1.0f);
    float norm = ns * nd;
    int pos = atomicAdd(&g_cursor[d], 1);
    g_csr[pos] = (unsigned long long)(unsigned)s |
                 ((unsigned long long)__float_as_uint(norm) << 32);
}

// ---------------- GEMM: h[n][0:32] = x[n][0:K] @ W[K][32] -------------------
template <int KDIM, int LAYER>
__global__ void gemm_kernel(const float* __restrict__ xin,
                            const float* __restrict__ W) {
    const float* x = (LAYER == 1) ? xin : (const float*)g_out1;
    float* h = (LAYER == 1) ? g_h1 : g_h2;

    __shared__ float Ws[KDIM * 32];
    for (int i = threadIdx.x; i < KDIM * 8; i += 128)
        ((float4*)Ws)[i] = ((const float4*)W)[i];
    __syncthreads();
    int node = blockIdx.x * 128 + threadIdx.x;
    if (node >= N_NODES) return;

    unsigned long long acc[16];
#pragma unroll
    for (int p = 0; p < 16; p++) acc[p] = 0ULL;

    const float4* xrow = (const float4*)(x + (size_t)node * KDIM);
#pragma unroll 4
    for (int k4 = 0; k4 < KDIM / 4; k4++) {
        float4 xv = xrow[k4];
        float xs[4] = {xv.x, xv.y, xv.z, xv.w};
#pragma unroll
        for (int j = 0; j < 4; j++) {
            unsigned long long xp = pack2(xs[j]);
            const ulonglong2* wr = (const ulonglong2*)(Ws + (k4 * 4 + j) * 32);
#pragma unroll
            for (int q = 0; q < 8; q++) {
                ulonglong2 ww = wr[q];
                ffma2(acc[2 * q],     xp, ww.x);
                ffma2(acc[2 * q + 1], xp, ww.y);
            }
        }
    }
    ulonglong2* outp = (ulonglong2*)(h + (size_t)node * 32);
#pragma unroll
    for (int q = 0; q < 8; q++) {
        ulonglong2 t; t.x = acc[2 * q]; t.y = acc[2 * q + 1];
        outp[q] = t;
    }
}

// ---------------- gather: one warp per node, register accumulation ----------
// LAYER 1: out1[n] = relu(sum + h1[n]*d2 + b1)
// LAYER 2: gsum[batch[n]] += dot(relu(sum + h2[n]*d2 + b2), Wo); gcnt += 1
template <int LAYER>
__global__ void gather_kernel(const void* batch,
                              const float* __restrict__ bvec,
                              const float* __restrict__ Wo) {
    int gidx = blockIdx.x * 256 + threadIdx.x;
    int n = gidx >> 5;
    int lane = gidx & 31;
    if (n >= N_NODES) return;

    const float* h = (LAYER == 1) ? g_h1 : g_h2;
    int start = g_off[n];
    int end = g_cursor[n];   // cursor after fill == CSR end

    float acc = 0.f;
    int i = start;
    // unroll-4 software pipeline: 4 independent csr loads, 4 independent row loads
    for (; i + 4 <= end; i += 4) {
        unsigned long long r0 = g_csr[i];
        unsigned long long r1 = g_csr[i + 1];
        unsigned long long r2 = g_csr[i + 2];
        unsigned long long r3 = g_csr[i + 3];
        float v0 = h[(size_t)(unsigned)(r0 & 0xffffffffu) * 32 + lane];
        float v1 = h[(size_t)(unsigned)(r1 & 0xffffffffu) * 32 + lane];
        float v2 = h[(size_t)(unsigned)(r2 & 0xffffffffu) * 32 + lane];
        float v3 = h[(size_t)(unsigned)(r3 & 0xffffffffu) * 32 + lane];
        acc = fmaf(v0, __uint_as_float((unsigned)(r0 >> 32)), acc);
        acc = fmaf(v1, __uint_as_float((unsigned)(r1 >> 32)), acc);
        acc = fmaf(v2, __uint_as_float((unsigned)(r2 >> 32)), acc);
        acc = fmaf(v3, __uint_as_float((unsigned)(r3 >> 32)), acc);
    }
    for (; i < end; i++) {
        unsigned long long r = g_csr[i];
        float v = h[(size_t)(unsigned)(r & 0xffffffffu) * 32 + lane];
        acc = fmaf(v, __uint_as_float((unsigned)(r >> 32)), acc);
    }

    // self-loop + bias + relu
    float hs = h[(size_t)n * 32 + lane];
    float d2 = 1.0f / ((float)g_degi[n] + 1.0f);
    float r = fmaxf(fmaf(hs, d2, acc) + __ldg(&bvec[lane]), 0.f);

    if (LAYER == 1) {
        g_out1[(size_t)n * 32 + lane] = r;
    } else {
        float p = r * __ldg(&Wo[lane]);
#pragma unroll
        for (int off = 16; off > 0; off >>= 1)
            p += __shfl_xor_sync(0xffffffffu, p, off);
        if (lane == 0) {
            int g;
            if (g_is64) g = (int)((const long long*)batch)[n];
            else        g = ((const int*)batch)[n];
            g = min(max(g, 0), N_GRAPHS - 1);
            atomicAdd(&g_gsum[g], p);
            atomicAdd(&g_gcnt[g], 1.0f);
        }
    }
}

__global__ void final_kernel(float* __restrict__ out,
                             const float* __restrict__ bo) {
    int i = blockIdx.x * 256 + threadIdx.x;
    if (i < N_GRAPHS)
        out[i] = g_gsum[i] / fmaxf(g_gcnt[i], 1.0f) + bo[0];
}

// ---------------- launch ----------------------------------------------------
extern "C" void kernel_launch(void* const* d_in, const int* in_sizes, int n_in,
                              void* d_out, int out_size) {
    const float* x   = (const float*)d_in[0];
    const void*  ei  = d_in[1];
    const void*  bat = d_in[2];
    const float* W1  = (const float*)d_in[3];
    const float* b1  = (const float*)d_in[4];
    const float* W2  = (const float*)d_in[5];
    const float* b2  = (const float*)d_in[6];
    const float* Wo  = (const float*)d_in[7];
    const float* bo  = (const float*)d_in[8];
    float* out = (float*)d_out;

    // zero via memset nodes (no allocation; symbol lookups only)
    void *p_degi = nullptr, *p_gsum = nullptr, *p_gcnt = nullptr;
    cudaGetSymbolAddress(&p_degi, g_degi);
    cudaGetSymbolAddress(&p_gsum, g_gsum);
    cudaGetSymbolAddress(&p_gcnt, g_gcnt);
    cudaMemsetAsync(p_degi, 0, N_NODES * sizeof(int));
    cudaMemsetAsync(p_gsum, 0, N_GRAPHS * sizeof(float));
    cudaMemsetAsync(p_gcnt, 0, N_GRAPHS * sizeof(float));

    detect_kernel<<<1, 256>>>(ei);
    deg_kernel<<<(N_EDGES + 255) / 256, 256>>>(ei);
    scan_kernel<<<1, 1024>>>();
    fill_kernel<<<(N_EDGES + 255) / 256, 256>>>(ei);

    // layer 1
    gemm_kernel<128, 1><<<(N_NODES + 127) / 128, 128>>>(x, W1);
    gather_kernel<1><<<(N_NODES * 32 + 255) / 256, 256>>>(bat, b1, Wo);

    // layer 2
    gemm_kernel<32, 2><<<(N_NODES + 127) / 128, 128>>>(nullptr, W2);
    gather_kernel<2><<<(N_NODES * 32 + 255) / 256, 256>>>(bat, b2, Wo);

    // head
    final_kernel<<<2, 256>>>(out, bo);
}

// round 4
// speedup vs baseline: 1.7691x; 1.7691x over previous
#include <cuda_runtime.h>
#include <cstdint>

#define N_NODES 100000
#define N_EDGES 1600000
#define N_GRAPHS 512

// ---------------- scratch (device globals; no allocation allowed) ----------
__device__ int                g_degi[N_NODES];
__device__ unsigned long long g_edge[N_EDGES];     // packed src | dst<<32
__device__ float              g_h1[N_NODES * 32];  // h1' = (x@W1)*dis
__device__ float              g_agg1[N_NODES * 32];
__device__ float              g_h2[N_NODES * 32];  // h2' = (out1@W2)*dis
__device__ float              g_agg2[N_NODES * 32];
__device__ float              g_gsum[N_GRAPHS];
__device__ float              g_gcnt[N_GRAPHS];
__device__ int                g_is64;

// ---------------- f32x2 helpers (Blackwell packed FFMA) ---------------------
__device__ __forceinline__ unsigned long long pack2(float x) {
    unsigned long long r;
    asm("mov.b64 %0, {%1, %1};" : "=l"(r) : "r"(__float_as_uint(x)));
    return r;
}
__device__ __forceinline__ void ffma2(unsigned long long& d,
                                      unsigned long long a,
                                      unsigned long long b) {
    asm("fma.rn.f32x2 %0, %1, %2, %0;" : "+l"(d) : "l"(a), "l"(b));
}
__device__ __forceinline__ float2 unpack2(unsigned long long v) {
    float2 f;
    asm("mov.b64 {%0, %1}, %2;" : "=f"(f.x), "=f"(f.y) : "l"(v));
    return f;
}

// ---------------- dtype detect + zero small arrays --------------------------
__global__ void detect_kernel(const void* ei) {
    if (blockIdx.x == 0) {
        __shared__ int bad;
        if (threadIdx.x == 0) bad = 0;
        __syncthreads();
        const unsigned long long* p = (const unsigned long long*)ei;
        for (int i = threadIdx.x; i < 1024; i += 256)
            if (p[i] >= (unsigned long long)N_NODES) bad = 1;
        __syncthreads();
        if (threadIdx.x == 0) g_is64 = bad ? 0 : 1;
    } else {
        int i = (blockIdx.x - 1) * 256 + threadIdx.x;
        if (i < N_GRAPHS) { g_gsum[i] = 0.f; g_gcnt[i] = 0.f; }
    }
}

// ---------------- prep: pack edges + degree histogram ------------------------
__global__ void prep_kernel(const void* ei) {
    int e = blockIdx.x * 256 + threadIdx.x;
    if (e >= N_EDGES) return;
    int s, d;
    if (g_is64) {
        const long long* p = (const long long*)ei;
        s = (int)p[e]; d = (int)p[N_EDGES + e];
    } else {
        const int* p = (const int*)ei;
        s = p[e]; d = p[N_EDGES + e];
    }
    s = min(max(s, 0), N_NODES - 1);
    d = min(max(d, 0), N_NODES - 1);
    g_edge[e] = (unsigned long long)(unsigned)s |
                ((unsigned long long)(unsigned)d << 32);
    atomicAdd(&g_degi[d], 1);
}

// ---------------- gemm1: h1' = (x @ W1) * dis; zero agg1 row ----------------
__global__ __launch_bounds__(128) void gemm1_kernel(const float* __restrict__ x,
                                                    const float* __restrict__ W) {
    __shared__ float Ws[128 * 32];
    for (int i = threadIdx.x; i < 128 * 8; i += 128)
        ((float4*)Ws)[i] = ((const float4*)W)[i];
    __syncthreads();
    int node = blockIdx.x * 128 + threadIdx.x;
    if (node >= N_NODES) return;

    unsigned long long acc[16];
#pragma unroll
    for (int p = 0; p < 16; p++) acc[p] = 0ULL;

    const float4* xrow = (const float4*)(x + (size_t)node * 128);
#pragma unroll 4
    for (int k4 = 0; k4 < 32; k4++) {
        float4 xv = xrow[k4];
        float xs[4] = {xv.x, xv.y, xv.z, xv.w};
#pragma unroll
        for (int j = 0; j < 4; j++) {
            unsigned long long xp = pack2(xs[j]);
            const ulonglong2* wr = (const ulonglong2*)(Ws + (k4 * 4 + j) * 32);
#pragma unroll
            for (int q = 0; q < 8; q++) {
                ulonglong2 ww = wr[q];
                ffma2(acc[2 * q],     xp, ww.x);
                ffma2(acc[2 * q + 1], xp, ww.y);
            }
        }
    }
    float dis = rsqrtf((float)g_degi[node] + 1.0f);
    float4* outp = (float4*)(g_h1 + (size_t)node * 32);
    float4* aggp = (float4*)(g_agg1 + (size_t)node * 32);
    float4 z = make_float4(0.f, 0.f, 0.f, 0.f);
#pragma unroll
    for (int q = 0; q < 8; q++) {
        float2 a = unpack2(acc[2 * q]);
        float2 b = unpack2(acc[2 * q + 1]);
        float4 o; o.x = a.x * dis; o.y = a.y * dis; o.z = b.x * dis; o.w = b.y * dis;
        outp[q] = o;
        aggp[q] = z;
    }
}

// ---------------- edge scatter: agg[dst] += h'[src] --------------------------
// 8 lanes per edge -> 128B coalesced gather + 128B vector red per edge
template <int LAYER>
__global__ __launch_bounds__(256) void scatter_kernel() {
    const float* h = (LAYER == 1) ? g_h1 : g_h2;
    float* agg = (LAYER == 1) ? g_agg1 : g_agg2;

    int idx = blockIdx.x * 256 + threadIdx.x;
    int e = idx >> 3;
    if (e >= N_EDGES) return;
    int c = idx & 7;
    unsigned long long ed = g_edge[e];
    int s = (int)(unsigned)(ed & 0xffffffffu);
    int d = (int)(unsigned)(ed >> 32);
    float4 v = ((const float4*)(h + (size_t)s * 32))[c];
    float* p = agg + (size_t)d * 32 + c * 4;
    asm volatile("red.global.add.v4.f32 [%0], {%1,%2,%3,%4};"
                 :: "l"(p), "f"(v.x), "f"(v.y), "f"(v.z), "f"(v.w)
                 : "memory");
}

// ---------------- gemm2: in = relu(dis*(agg1+h1')+b1); h2' = (in@W2)*dis ----
__global__ __launch_bounds__(128) void gemm2_kernel(const float* __restrict__ W,
                                                    const float* __restrict__ b1) {
    __shared__ float Ws[32 * 32];
    for (int i = threadIdx.x; i < 32 * 8; i += 128)
        ((float4*)Ws)[i] = ((const float4*)W)[i];
    __syncthreads();
    int node = blockIdx.x * 128 + threadIdx.x;
    if (node >= N_NODES) return;

    float dis = rsqrtf((float)g_degi[node] + 1.0f);
    const float4* aggp = (const float4*)(g_agg1 + (size_t)node * 32);
    const float4* hp   = (const float4*)(g_h1 + (size_t)node * 32);
    float in[32];
#pragma unroll
    for (int c = 0; c < 8; c++) {
        float4 a = aggp[c], h = hp[c];
        float4 b = ((const float4*)b1)[c];
        in[4 * c + 0] = fmaxf(fmaf(dis, a.x + h.x, b.x), 0.f);
        in[4 * c + 1] = fmaxf(fmaf(dis, a.y + h.y, b.y), 0.f);
        in[4 * c + 2] = fmaxf(fmaf(dis, a.z + h.z, b.z), 0.f);
        in[4 * c + 3] = fmaxf(fmaf(dis, a.w + h.w, b.w), 0.f);
    }

    unsigned long long acc[16];
#pragma unroll
    for (int p = 0; p < 16; p++) acc[p] = 0ULL;
#pragma unroll
    for (int k = 0; k < 32; k++) {
        unsigned long long xp = pack2(in[k]);
        const ulonglong2* wr = (const ulonglong2*)(Ws + k * 32);
#pragma unroll
        for (int q = 0; q < 8; q++) {
            ulonglong2 ww = wr[q];
            ffma2(acc[2 * q],     xp, ww.x);
            ffma2(acc[2 * q + 1], xp, ww.y);
        }
    }
    float4* outp = (float4*)(g_h2 + (size_t)node * 32);
    float4* agg2p = (float4*)(g_agg2 + (size_t)node * 32);
    float4 z = make_float4(0.f, 0.f, 0.f, 0.f);
#pragma unroll
    for (int q = 0; q < 8; q++) {
        float2 a = unpack2(acc[2 * q]);
        float2 b = unpack2(acc[2 * q + 1]);
        float4 o; o.x = a.x * dis; o.y = a.y * dis; o.z = b.x * dis; o.w = b.y * dis;
        outp[q] = o;
        agg2p[q] = z;
    }
}

// ---------------- pool: fold relu2 + bias + dot(Wo) + segment sums ----------
__global__ void pool_kernel(const void* batch,
                            const float* __restrict__ b2,
                            const float* __restrict__ Wo) {
    int n = blockIdx.x * 256 + threadIdx.x;
    if (n >= N_NODES) return;
    int g;
    if (g_is64) g = (int)((const long long*)batch)[n];
    else        g = ((const int*)batch)[n];
    g = min(max(g, 0), N_GRAPHS - 1);
    float dis = rsqrtf((float)g_degi[n] + 1.0f);
    const float4* a2 = (const float4*)(g_agg2 + (size_t)n * 32);
    const float4* hh = (const float4*)(g_h2 + (size_t)n * 32);
    float s = 0.f;
#pragma unroll
    for (int c = 0; c < 8; c++) {
        float4 a = a2[c], h = hh[c];
        float4 b = ((const float4*)b2)[c];
        float4 w = ((const float4*)Wo)[c];
        s += fmaxf(fmaf(dis, a.x + h.x, b.x), 0.f) * w.x;
        s += fmaxf(fmaf(dis, a.y + h.y, b.y), 0.f) * w.y;
        s += fmaxf(fmaf(dis, a.z + h.z, b.z), 0.f) * w.z;
        s += fmaxf(fmaf(dis, a.w + h.w, b.w), 0.f) * w.w;
    }
    atomicAdd(&g_gsum[g], s);
    atomicAdd(&g_gcnt[g], 1.0f);
}

__global__ void final_kernel(float* __restrict__ out,
                             const float* __restrict__ bo) {
    int i = blockIdx.x * 256 + threadIdx.x;
    if (i < N_GRAPHS)
        out[i] = g_gsum[i] / fmaxf(g_gcnt[i], 1.0f) + bo[0];
}

// ---------------- launch ----------------------------------------------------
extern "C" void kernel_launch(void* const* d_in, const int* in_sizes, int n_in,
                              void* d_out, int out_size) {
    const float* x   = (const float*)d_in[0];
    const void*  ei  = d_in[1];
    const void*  bat = d_in[2];
    const float* W1  = (const float*)d_in[3];
    const float* b1  = (const float*)d_in[4];
    const float* W2  = (const float*)d_in[5];
    const float* b2  = (const float*)d_in[6];
    const float* Wo  = (const float*)d_in[7];
    const float* bo  = (const float*)d_in[8];
    float* out = (float*)d_out;

    void* p_degi = nullptr;
    cudaGetSymbolAddress(&p_degi, g_degi);
    cudaMemsetAsync(p_degi, 0, N_NODES * sizeof(int));

    detect_kernel<<<1 + (N_GRAPHS + 255) / 256, 256>>>(ei);
    prep_kernel<<<(N_EDGES + 255) / 256, 256>>>(ei);

    // layer 1
    gemm1_kernel<<<(N_NODES + 127) / 128, 128>>>(x, W1);
    scatter_kernel<1><<<(N_EDGES * 8 + 255) / 256, 256>>>();

    // layer 2 (fuse1 folded into gemm2 input stage)
    gemm2_kernel<<<(N_NODES + 127) / 128, 128>>>(W2, b1);
    scatter_kernel<2><<<(N_EDGES * 8 + 255) / 256, 256>>>();

    // pooling + head
    pool_kernel<<<(N_NODES + 255) / 256, 256>>>(bat, b2, Wo);
    final_kernel<<<2, 256>>>(out, bo);
}

// round 5
// speedup vs baseline: 1.9091x; 1.0791x over previous
#include <cuda_runtime.h>
#include <cuda_fp16.h>
#include <cstdint>

#define N_NODES 100000
#define N_EDGES 1600000
#define N_GRAPHS 512

// ---------------- scratch (device globals; no allocation allowed) ----------
__device__ int                g_degi[N_NODES];
__device__ unsigned long long g_edge[N_EDGES];      // packed src | dst<<32
__device__ uint2              g_h1h[N_NODES * 8];   // h1' = (x@W1)*dis, fp16 (64B/row)
__device__ float              g_agg1[N_NODES * 32];
__device__ uint2              g_h2h[N_NODES * 8];   // h2' = (out1@W2)*dis, fp16
__device__ float              g_agg2[N_NODES * 32];
__device__ float              g_gsum[N_GRAPHS];
__device__ float              g_gcnt[N_GRAPHS];
__device__ int                g_is64;

// ---------------- f32x2 helpers (Blackwell packed FFMA) ---------------------
__device__ __forceinline__ unsigned long long pack2(float x) {
    unsigned long long r;
    asm("mov.b64 %0, {%1, %1};" : "=l"(r) : "r"(__float_as_uint(x)));
    return r;
}
__device__ __forceinline__ void ffma2(unsigned long long& d,
                                      unsigned long long a,
                                      unsigned long long b) {
    asm("fma.rn.f32x2 %0, %1, %2, %0;" : "+l"(d) : "l"(a), "l"(b));
}
__device__ __forceinline__ float2 unpack2(unsigned long long v) {
    float2 f;
    asm("mov.b64 {%0, %1}, %2;" : "=f"(f.x), "=f"(f.y) : "l"(v));
    return f;
}
__device__ __forceinline__ unsigned h2u(__half2 h) {
    return *(unsigned*)&h;
}
__device__ __forceinline__ float2 u2f2(unsigned u) {
    return __half22float2(*(__half2*)&u);
}

// ---------------- dtype detect + zero small arrays --------------------------
__global__ void detect_kernel(const void* ei) {
    if (blockIdx.x == 0) {
        __shared__ int bad;
        if (threadIdx.x == 0) bad = 0;
        __syncthreads();
        const unsigned long long* p = (const unsigned long long*)ei;
        for (int i = threadIdx.x; i < 1024; i += 256)
            if (p[i] >= (unsigned long long)N_NODES) bad = 1;
        __syncthreads();
        if (threadIdx.x == 0) g_is64 = bad ? 0 : 1;
    } else {
        int i = (blockIdx.x - 1) * 256 + threadIdx.x;
        if (i < N_GRAPHS) { g_gsum[i] = 0.f; g_gcnt[i] = 0.f; }
    }
}

// ---------------- prep: pack edges + degree histogram ------------------------
__global__ void prep_kernel(const void* ei) {
    int e = blockIdx.x * 256 + threadIdx.x;
    if (e >= N_EDGES) return;
    int s, d;
    if (g_is64) {
        const long long* p = (const long long*)ei;
        s = (int)p[e]; d = (int)p[N_EDGES + e];
    } else {
        const int* p = (const int*)ei;
        s = p[e]; d = p[N_EDGES + e];
    }
    s = min(max(s, 0), N_NODES - 1);
    d = min(max(d, 0), N_NODES - 1);
    g_edge[e] = (unsigned long long)(unsigned)s |
                ((unsigned long long)(unsigned)d << 32);
    atomicAdd(&g_degi[d], 1);
}

// ---------------- gemm1: h1' = (x @ W1) * dis (fp16); zero agg1 row ---------
__global__ __launch_bounds__(128) void gemm1_kernel(const float* __restrict__ x,
                                                    const float* __restrict__ W) {
    __shared__ float Ws[128 * 32];
    for (int i = threadIdx.x; i < 128 * 8; i += 128)
        ((float4*)Ws)[i] = ((const float4*)W)[i];
    __syncthreads();
    int node = blockIdx.x * 128 + threadIdx.x;
    if (node >= N_NODES) return;

    unsigned long long acc[16];
#pragma unroll
    for (int p = 0; p < 16; p++) acc[p] = 0ULL;

    const float4* xrow = (const float4*)(x + (size_t)node * 128);
#pragma unroll 4
    for (int k4 = 0; k4 < 32; k4++) {
        float4 xv = xrow[k4];
        float xs[4] = {xv.x, xv.y, xv.z, xv.w};
#pragma unroll
        for (int j = 0; j < 4; j++) {
            unsigned long long xp = pack2(xs[j]);
            const ulonglong2* wr = (const ulonglong2*)(Ws + (k4 * 4 + j) * 32);
#pragma unroll
            for (int q = 0; q < 8; q++) {
                ulonglong2 ww = wr[q];
                ffma2(acc[2 * q],     xp, ww.x);
                ffma2(acc[2 * q + 1], xp, ww.y);
            }
        }
    }
    float dis = rsqrtf((float)g_degi[node] + 1.0f);
    uint2* outp = g_h1h + (size_t)node * 8;
    float4* aggp = (float4*)(g_agg1 + (size_t)node * 32);
    float4 z = make_float4(0.f, 0.f, 0.f, 0.f);
#pragma unroll
    for (int q = 0; q < 8; q++) {
        float2 a = unpack2(acc[2 * q]);
        float2 b = unpack2(acc[2 * q + 1]);
        uint2 t;
        t.x = h2u(__floats2half2_rn(a.x * dis, a.y * dis));
        t.y = h2u(__floats2half2_rn(b.x * dis, b.y * dis));
        outp[q] = t;
        aggp[q] = z;
    }
}

// ---------------- edge scatter: agg[dst] += h'[src] --------------------------
// 8 lanes per edge; 4 independent edges per thread for MLP=4
template <int LAYER>
__global__ __launch_bounds__(256) void scatter_kernel() {
    const uint2* h = (LAYER == 1) ? g_h1h : g_h2h;
    float* agg = (LAYER == 1) ? g_agg1 : g_agg2;
    const int Q = N_EDGES / 4;

    int idx = blockIdx.x * 256 + threadIdx.x;
    int e0 = idx >> 3;
    if (e0 >= Q) return;
    int c = idx & 7;

    unsigned long long ed0 = g_edge[e0];
    unsigned long long ed1 = g_edge[e0 + Q];
    unsigned long long ed2 = g_edge[e0 + 2 * Q];
    unsigned long long ed3 = g_edge[e0 + 3 * Q];

    uint2 v0 = h[(size_t)(unsigned)(ed0 & 0xffffffffu) * 8 + c];
    uint2 v1 = h[(size_t)(unsigned)(ed1 & 0xffffffffu) * 8 + c];
    uint2 v2 = h[(size_t)(unsigned)(ed2 & 0xffffffffu) * 8 + c];
    uint2 v3 = h[(size_t)(unsigned)(ed3 & 0xffffffffu) * 8 + c];

#pragma unroll
    for (int j = 0; j < 4; j++) {
        unsigned long long ed = (j == 0) ? ed0 : (j == 1) ? ed1 : (j == 2) ? ed2 : ed3;
        uint2 v = (j == 0) ? v0 : (j == 1) ? v1 : (j == 2) ? v2 : v3;
        float2 f01 = u2f2(v.x);
        float2 f23 = u2f2(v.y);
        float* p = agg + (size_t)(unsigned)(ed >> 32) * 32 + c * 4;
        asm volatile("red.global.add.v4.f32 [%0], {%1,%2,%3,%4};"
                     :: "l"(p), "f"(f01.x), "f"(f01.y), "f"(f23.x), "f"(f23.y)
                     : "memory");
    }
}

// ---------------- gemm2: in = relu(dis*(agg1+h1')+b1); h2' = (in@W2)*dis ----
__global__ __launch_bounds__(128) void gemm2_kernel(const float* __restrict__ W,
                                                    const float* __restrict__ b1) {
    __shared__ float Ws[32 * 32];
    for (int i = threadIdx.x; i < 32 * 8; i += 128)
        ((float4*)Ws)[i] = ((const float4*)W)[i];
    __syncthreads();
    int node = blockIdx.x * 128 + threadIdx.x;
    if (node >= N_NODES) return;

    float dis = rsqrtf((float)g_degi[node] + 1.0f);
    const float4* aggp = (const float4*)(g_agg1 + (size_t)node * 32);
    const uint2* hp = g_h1h + (size_t)node * 8;
    float in[32];
#pragma unroll
    for (int cq = 0; cq < 8; cq++) {
        float4 a = aggp[cq];
        uint2 hv = hp[cq];
        float2 h01 = u2f2(hv.x), h23 = u2f2(hv.y);
        float4 b = ((const float4*)b1)[cq];
        in[4 * cq + 0] = fmaxf(fmaf(dis, a.x + h01.x, b.x), 0.f);
        in[4 * cq + 1] = fmaxf(fmaf(dis, a.y + h01.y, b.y), 0.f);
        in[4 * cq + 2] = fmaxf(fmaf(dis, a.z + h23.x, b.z), 0.f);
        in[4 * cq + 3] = fmaxf(fmaf(dis, a.w + h23.y, b.w), 0.f);
    }

    unsigned long long acc[16];
#pragma unroll
    for (int p = 0; p < 16; p++) acc[p] = 0ULL;
#pragma unroll
    for (int k = 0; k < 32; k++) {
        unsigned long long xp = pack2(in[k]);
        const ulonglong2* wr = (const ulonglong2*)(Ws + k * 32);
#pragma unroll
        for (int q = 0; q < 8; q++) {
            ulonglong2 ww = wr[q];
            ffma2(acc[2 * q],     xp, ww.x);
            ffma2(acc[2 * q + 1], xp, ww.y);
        }
    }
    uint2* outp = g_h2h + (size_t)node * 8;
    float4* agg2p = (float4*)(g_agg2 + (size_t)node * 32);
    float4 z = make_float4(0.f, 0.f, 0.f, 0.f);
#pragma unroll
    for (int q = 0; q < 8; q++) {
        float2 a = unpack2(acc[2 * q]);
        float2 b = unpack2(acc[2 * q + 1]);
        uint2 t;
        t.x = h2u(__floats2half2_rn(a.x * dis, a.y * dis));
        t.y = h2u(__floats2half2_rn(b.x * dis, b.y * dis));
        outp[q] = t;
        agg2p[q] = z;
    }
}

// ---------------- pool: fold relu2 + bias + dot(Wo) + segment sums ----------
__global__ void pool_kernel(const void* batch,
                            const float* __restrict__ b2,
                            const float* __restrict__ Wo) {
    int n = blockIdx.x * 256 + threadIdx.x;
    if (n >= N_NODES) return;
    int g;
    if (g_is64) g = (int)((const long long*)batch)[n];
    else        g = ((const int*)batch)[n];
    g = min(max(g, 0), N_GRAPHS - 1);
    float dis = rsqrtf((float)g_degi[n] + 1.0f);
    const float4* a2 = (const float4*)(g_agg2 + (size_t)n * 32);
    const uint2* hh = g_h2h + (size_t)n * 8;
    float s = 0.f;
#pragma unroll
    for (int c = 0; c < 8; c++) {
        float4 a = a2[c];
        uint2 hv = hh[c];
        float2 h01 = u2f2(hv.x), h23 = u2f2(hv.y);
        float4 b = ((const float4*)b2)[c];
        float4 w = ((const float4*)Wo)[c];
        s += fmaxf(fmaf(dis, a.x + h01.x, b.x), 0.f) * w.x;
        s += fmaxf(fmaf(dis, a.y + h01.y, b.y), 0.f) * w.y;
        s += fmaxf(fmaf(dis, a.z + h23.x, b.z), 0.f) * w.z;
        s += fmaxf(fmaf(dis, a.w + h23.y, b.w), 0.f) * w.w;
    }
    atomicAdd(&g_gsum[g], s);
    atomicAdd(&g_gcnt[g], 1.0f);
}

__global__ void final_kernel(float* __restrict__ out,
                             const float* __restrict__ bo) {
    int i = blockIdx.x * 256 + threadIdx.x;
    if (i < N_GRAPHS)
        out[i] = g_gsum[i] / fmaxf(g_gcnt[i], 1.0f) + bo[0];
}

// ---------------- launch ----------------------------------------------------
extern "C" void kernel_launch(void* const* d_in, const int* in_sizes, int n_in,
                              void* d_out, int out_size) {
    const float* x   = (const float*)d_in[0];
    const void*  ei  = d_in[1];
    const void*  bat = d_in[2];
    const float* W1  = (const float*)d_in[3];
    const float* b1  = (const float*)d_in[4];
    const float* W2  = (const float*)d_in[5];
    const float* b2  = (const float*)d_in[6];
    const float* Wo  = (const float*)d_in[7];
    const float* bo  = (const float*)d_in[8];
    float* out = (float*)d_out;

    void* p_degi = nullptr;
    cudaGetSymbolAddress(&p_degi, g_degi);
    cudaMemsetAsync(p_degi, 0, N_NODES * sizeof(int));

    detect_kernel<<<1 + (N_GRAPHS + 255) / 256, 256>>>(ei);
    prep_kernel<<<(N_EDGES + 255) / 256, 256>>>(ei);

    // layer 1
    gemm1_kernel<<<(N_NODES + 127) / 128, 128>>>(x, W1);
    scatter_kernel<1><<<(N_EDGES / 4 * 8 + 255) / 256, 256>>>();

    // layer 2 (fuse1 folded into gemm2 input stage)
    gemm2_kernel<<<(N_NODES + 127) / 128, 128>>>(W2, b1);
    scatter_kernel<2><<<(N_EDGES / 4 * 8 + 255) / 256, 256>>>();

    // pooling + head
    pool_kernel<<<(N_NODES + 255) / 256, 256>>>(bat, b2, Wo);
    final_kernel<<<2, 256>>>(out, bo);
}

// round 6
// speedup vs baseline: 2.2698x; 1.1889x over previous
#include <cuda_runtime.h>
#include <cuda_fp16.h>
#include <cstdint>

#define N_NODES 100000
#define N_EDGES 1600000
#define N_GRAPHS 512

// ---------------- scratch (device globals; no allocation allowed) ----------
__device__ int                g_degi[N_NODES];
__device__ unsigned long long g_edge[N_EDGES];      // packed src | dst<<32
__device__ uint2              g_h1h[N_NODES * 8];   // h1' = (x@W1)*dis, fp16
__device__ uint2              g_agg1h[N_NODES * 8]; // fp16 accumulators
__device__ uint2              g_h2h[N_NODES * 8];   // h2' fp16
__device__ uint2              g_agg2h[N_NODES * 8];
__device__ float              g_gsum[N_GRAPHS];
__device__ float              g_gcnt[N_GRAPHS];
__device__ int                g_done;

// ---------------- f32x2 helpers (Blackwell packed FFMA) ---------------------
__device__ __forceinline__ unsigned long long pack2(float x) {
    unsigned long long r;
    asm("mov.b64 %0, {%1, %1};" : "=l"(r) : "r"(__float_as_uint(x)));
    return r;
}
__device__ __forceinline__ void ffma2(unsigned long long& d,
                                      unsigned long long a,
                                      unsigned long long b) {
    asm("fma.rn.f32x2 %0, %1, %2, %0;" : "+l"(d) : "l"(a), "l"(b));
}
__device__ __forceinline__ float2 unpack2(unsigned long long v) {
    float2 f;
    asm("mov.b64 {%0, %1}, %2;" : "=f"(f.x), "=f"(f.y) : "l"(v));
    return f;
}
__device__ __forceinline__ unsigned h2u(__half2 h) { return *(unsigned*)&h; }
__device__ __forceinline__ float2 u2f2(unsigned u) {
    return __half22float2(*(__half2*)&u);
}

// per-block dtype detection: warp ballot over first 64 u64 words of edge_index
__device__ __forceinline__ int detect_is64(const void* ei) {
    __shared__ int s_is64;
    if (threadIdx.x < 32) {
        const unsigned long long* p = (const unsigned long long*)ei;
        unsigned long long v0 = p[threadIdx.x];
        unsigned long long v1 = p[32 + threadIdx.x];
        unsigned m = __ballot_sync(0xffffffffu,
            (v0 >= (unsigned long long)N_NODES) || (v1 >= (unsigned long long)N_NODES));
        if (threadIdx.x == 0) s_is64 = m ? 0 : 1;
    }
    __syncthreads();
    return s_is64;
}

// ---------------- prep: detect + pack edges + degree hist + zero smalls -----
__global__ void prep_kernel(const void* ei) {
    int is64 = detect_is64(ei);
    if (blockIdx.x == 0) {
        for (int i = threadIdx.x; i < N_GRAPHS; i += 256) {
            g_gsum[i] = 0.f; g_gcnt[i] = 0.f;
        }
        if (threadIdx.x == 0) g_done = 0;
    }
    int e = blockIdx.x * 256 + threadIdx.x;
    if (e >= N_EDGES) return;
    int s, d;
    if (is64) {
        const long long* p = (const long long*)ei;
        s = (int)p[e]; d = (int)p[N_EDGES + e];
    } else {
        const int* p = (const int*)ei;
        s = p[e]; d = p[N_EDGES + e];
    }
    s = min(max(s, 0), N_NODES - 1);
    d = min(max(d, 0), N_NODES - 1);
    g_edge[e] = (unsigned long long)(unsigned)s |
                ((unsigned long long)(unsigned)d << 32);
    atomicAdd(&g_degi[d], 1);
}

// ---------------- gemm1: h1' = (x @ W1) * dis (fp16); zero agg1 row ---------
__global__ __launch_bounds__(128) void gemm1_kernel(const float* __restrict__ x,
                                                    const float* __restrict__ W) {
    __shared__ float Ws[128 * 32];
    for (int i = threadIdx.x; i < 128 * 8; i += 128)
        ((float4*)Ws)[i] = ((const float4*)W)[i];
    __syncthreads();
    int node = blockIdx.x * 128 + threadIdx.x;
    if (node >= N_NODES) return;

    unsigned long long acc[16];
#pragma unroll
    for (int p = 0; p < 16; p++) acc[p] = 0ULL;

    const float4* xrow = (const float4*)(x + (size_t)node * 128);
#pragma unroll 4
    for (int k4 = 0; k4 < 32; k4++) {
        float4 xv = xrow[k4];
        float xs[4] = {xv.x, xv.y, xv.z, xv.w};
#pragma unroll
        for (int j = 0; j < 4; j++) {
            unsigned long long xp = pack2(xs[j]);
            const ulonglong2* wr = (const ulonglong2*)(Ws + (k4 * 4 + j) * 32);
#pragma unroll
            for (int q = 0; q < 8; q++) {
                ulonglong2 ww = wr[q];
                ffma2(acc[2 * q],     xp, ww.x);
                ffma2(acc[2 * q + 1], xp, ww.y);
            }
        }
    }
    float dis = rsqrtf((float)g_degi[node] + 1.0f);
    uint2* outp = g_h1h + (size_t)node * 8;
    uint2* aggp = g_agg1h + (size_t)node * 8;
    uint2 z; z.x = 0u; z.y = 0u;
#pragma unroll
    for (int q = 0; q < 8; q++) {
        float2 a = unpack2(acc[2 * q]);
        float2 b = unpack2(acc[2 * q + 1]);
        uint2 t;
        t.x = h2u(__floats2half2_rn(a.x * dis, a.y * dis));
        t.y = h2u(__floats2half2_rn(b.x * dis, b.y * dis));
        outp[q] = t;
        aggp[q] = z;
    }
}

// ---------------- edge scatter: agg[dst] += h'[src] (all fp16) ---------------
// 8 lanes per edge (8B each); 4 independent edges per thread for MLP=4
template <int LAYER>
__global__ __launch_bounds__(256) void scatter_kernel() {
    const uint2* h = (LAYER == 1) ? g_h1h : g_h2h;
    uint2* agg = (LAYER == 1) ? g_agg1h : g_agg2h;
    const int Q = N_EDGES / 4;

    int idx = blockIdx.x * 256 + threadIdx.x;
    int e0 = idx >> 3;
    if (e0 >= Q) return;
    int c = idx & 7;

    unsigned long long ed0 = g_edge[e0];
    unsigned long long ed1 = g_edge[e0 + Q];
    unsigned long long ed2 = g_edge[e0 + 2 * Q];
    unsigned long long ed3 = g_edge[e0 + 3 * Q];

    uint2 v0 = h[(size_t)(unsigned)(ed0 & 0xffffffffu) * 8 + c];
    uint2 v1 = h[(size_t)(unsigned)(ed1 & 0xffffffffu) * 8 + c];
    uint2 v2 = h[(size_t)(unsigned)(ed2 & 0xffffffffu) * 8 + c];
    uint2 v3 = h[(size_t)(unsigned)(ed3 & 0xffffffffu) * 8 + c];

#pragma unroll
    for (int j = 0; j < 4; j++) {
        unsigned long long ed = (j == 0) ? ed0 : (j == 1) ? ed1 : (j == 2) ? ed2 : ed3;
        uint2 v = (j == 0) ? v0 : (j == 1) ? v1 : (j == 2) ? v2 : v3;
        uint2* p = agg + (size_t)(unsigned)(ed >> 32) * 8 + c;
        asm volatile("red.global.add.noftz.v2.f16x2 [%0], {%1,%2};"
                     :: "l"(p), "r"(v.x), "r"(v.y)
                     : "memory");
    }
}

// ---------------- gemm2: in = relu(dis*(agg1+h1')+b1); h2' = (in@W2)*dis ----
__global__ __launch_bounds__(128) void gemm2_kernel(const float* __restrict__ W,
                                                    const float* __restrict__ b1) {
    __shared__ float Ws[32 * 32];
    for (int i = threadIdx.x; i < 32 * 8; i += 128)
        ((float4*)Ws)[i] = ((const float4*)W)[i];
    __syncthreads();
    int node = blockIdx.x * 128 + threadIdx.x;
    if (node >= N_NODES) return;

    float dis = rsqrtf((float)g_degi[node] + 1.0f);
    const uint2* aggp = g_agg1h + (size_t)node * 8;
    const uint2* hp = g_h1h + (size_t)node * 8;
    float in[32];
#pragma unroll
    for (int cq = 0; cq < 8; cq++) {
        uint2 av = aggp[cq];
        uint2 hv = hp[cq];
        float2 a01 = u2f2(av.x), a23 = u2f2(av.y);
        float2 h01 = u2f2(hv.x), h23 = u2f2(hv.y);
        float4 b = ((const float4*)b1)[cq];
        in[4 * cq + 0] = fmaxf(fmaf(dis, a01.x + h01.x, b.x), 0.f);
        in[4 * cq + 1] = fmaxf(fmaf(dis, a01.y + h01.y, b.y), 0.f);
        in[4 * cq + 2] = fmaxf(fmaf(dis, a23.x + h23.x, b.z), 0.f);
        in[4 * cq + 3] = fmaxf(fmaf(dis, a23.y + h23.y, b.w), 0.f);
    }

    unsigned long long acc[16];
#pragma unroll
    for (int p = 0; p < 16; p++) acc[p] = 0ULL;
#pragma unroll
    for (int k = 0; k < 32; k++) {
        unsigned long long xp = pack2(in[k]);
        const ulonglong2* wr = (const ulonglong2*)(Ws + k * 32);
#pragma unroll
        for (int q = 0; q < 8; q++) {
            ulonglong2 ww = wr[q];
            ffma2(acc[2 * q],     xp, ww.x);
            ffma2(acc[2 * q + 1], xp, ww.y);
        }
    }
    uint2* outp = g_h2h + (size_t)node * 8;
    uint2* agg2p = g_agg2h + (size_t)node * 8;
    uint2 z; z.x = 0u; z.y = 0u;
#pragma unroll
    for (int q = 0; q < 8; q++) {
        float2 a = unpack2(acc[2 * q]);
        float2 b = unpack2(acc[2 * q + 1]);
        uint2 t;
        t.x = h2u(__floats2half2_rn(a.x * dis, a.y * dis));
        t.y = h2u(__floats2half2_rn(b.x * dis, b.y * dis));
        outp[q] = t;
        agg2p[q] = z;
    }
}

// ---------------- pool: relu2 + bias + dot(Wo) + segment sums + final -------
__global__ void pool_kernel(const void* ei, const void* batch,
                            const float* __restrict__ b2,
                            const float* __restrict__ Wo,
                            const float* __restrict__ bo,
                            float* __restrict__ out) {
    int is64 = detect_is64(ei);
    int n = blockIdx.x * 256 + threadIdx.x;
    if (n < N_NODES) {
        int g;
        if (is64) g = (int)((const long long*)batch)[n];
        else      g = ((const int*)batch)[n];
        g = min(max(g, 0), N_GRAPHS - 1);
        float dis = rsqrtf((float)g_degi[n] + 1.0f);
        const uint2* a2 = g_agg2h + (size_t)n * 8;
        const uint2* hh = g_h2h + (size_t)n * 8;
        float s = 0.f;
#pragma unroll
        for (int c = 0; c < 8; c++) {
            uint2 av = a2[c];
            uint2 hv = hh[c];
            float2 a01 = u2f2(av.x), a23 = u2f2(av.y);
            float2 h01 = u2f2(hv.x), h23 = u2f2(hv.y);
            float4 b = ((const float4*)b2)[c];
            float4 w = ((const float4*)Wo)[c];
            s += fmaxf(fmaf(dis, a01.x + h01.x, b.x), 0.f) * w.x;
            s += fmaxf(fmaf(dis, a01.y + h01.y, b.y), 0.f) * w.y;
            s += fmaxf(fmaf(dis, a23.x + h23.x, b.z), 0.f) * w.z;
            s += fmaxf(fmaf(dis, a23.y + h23.y, b.w), 0.f) * w.w;
        }
        atomicAdd(&g_gsum[g], s);
        atomicAdd(&g_gcnt[g], 1.0f);
    }

    // last-block finalize
    __threadfence();
    __syncthreads();
    __shared__ int s_last;
    if (threadIdx.x == 0) {
        int t = atomicAdd(&g_done, 1);
        s_last = (t == (int)gridDim.x - 1) ? 1 : 0;
    }
    __syncthreads();
    if (s_last) {
        float bias = bo[0];
        for (int i = threadIdx.x; i < N_GRAPHS; i += 256) {
            float sv = atomicAdd(&g_gsum[i], 0.0f);   // coherent read
            float cv = atomicAdd(&g_gcnt[i], 0.0f);
            out[i] = sv / fmaxf(cv, 1.0f) + bias;
        }
        __syncthreads();
        if (threadIdx.x == 0) g_done = 0;   // self-reset for graph replay
    }
}

// ---------------- launch ----------------------------------------------------
extern "C" void kernel_launch(void* const* d_in, const int* in_sizes, int n_in,
                              void* d_out, int out_size) {
    const float* x   = (const float*)d_in[0];
    const void*  ei  = d_in[1];
    const void*  bat = d_in[2];
    const float* W1  = (const float*)d_in[3];
    const float* b1  = (const float*)d_in[4];
    const float* W2  = (const float*)d_in[5];
    const float* b2  = (const float*)d_in[6];
    const float* Wo  = (const float*)d_in[7];
    const float* bo  = (const float*)d_in[8];
    float* out = (float*)d_out;

    void* p_degi = nullptr;
    cudaGetSymbolAddress(&p_degi, g_degi);
    cudaMemsetAsync(p_degi, 0, N_NODES * sizeof(int));

    prep_kernel<<<(N_EDGES + 255) / 256, 256>>>(ei);

    // layer 1
    gemm1_kernel<<<(N_NODES + 127) / 128, 128>>>(x, W1);
    scatter_kernel<1><<<(N_EDGES / 4 * 8 + 255) / 256, 256>>>();

    // layer 2 (fuse1 folded into gemm2 input stage)
    gemm2_kernel<<<(N_NODES + 127) / 128, 128>>>(W2, b1);
    scatter_kernel<2><<<(N_EDGES / 4 * 8 + 255) / 256, 256>>>();

    // pooling + head (final fold via last-block)
    pool_kernel<<<(N_NODES + 255) / 256, 256>>>(ei, bat, b2, Wo, bo, out);
}

// round 7
// speedup vs baseline: 2.6019x; 1.1463x over previous
#include <cuda_runtime.h>
#include <cuda_fp16.h>
#include <cstdint>

#define N_NODES 100000
#define N_EDGES 1600000
#define N_GRAPHS 512

// ---------------- scratch (device globals; no allocation allowed) ----------
__device__ int                g_degi[N_NODES];
__device__ unsigned long long g_edge[N_EDGES];      // packed src | dst<<32
__device__ uint2              g_h1h[N_NODES * 8];   // h1' = (x@W1)*dis, fp16
__device__ uint2              g_agg1h[N_NODES * 8]; // fp16 accumulators
__device__ uint2              g_h2h[N_NODES * 8];   // h2' fp16
__device__ uint2              g_agg2h[N_NODES * 8];
__device__ float              g_gsum[N_GRAPHS];
__device__ float              g_gcnt[N_GRAPHS];
__device__ int                g_done;

// ---------------- f32x2 helpers (Blackwell packed FFMA) ---------------------
__device__ __forceinline__ unsigned long long pack2(float x) {
    unsigned long long r;
    asm("mov.b64 %0, {%1, %1};" : "=l"(r) : "r"(__float_as_uint(x)));
    return r;
}
__device__ __forceinline__ void ffma2(unsigned long long& d,
                                      unsigned long long a,
                                      unsigned long long b) {
    asm("fma.rn.f32x2 %0, %1, %2, %0;" : "+l"(d) : "l"(a), "l"(b));
}
__device__ __forceinline__ float2 unpack2(unsigned long long v) {
    float2 f;
    asm("mov.b64 {%0, %1}, %2;" : "=f"(f.x), "=f"(f.y) : "l"(v));
    return f;
}
__device__ __forceinline__ unsigned h2u(__half2 h) { return *(unsigned*)&h; }
__device__ __forceinline__ float2 u2f2(unsigned u) {
    return __half22float2(*(__half2*)&u);
}

// per-block dtype detection: warp ballot over first 64 u64 words of edge_index
__device__ __forceinline__ int detect_is64(const void* ei) {
    __shared__ int s_is64;
    if (threadIdx.x < 32) {
        const unsigned long long* p = (const unsigned long long*)ei;
        unsigned long long v0 = p[threadIdx.x];
        unsigned long long v1 = p[32 + threadIdx.x];
        unsigned m = __ballot_sync(0xffffffffu,
            (v0 >= (unsigned long long)N_NODES) || (v1 >= (unsigned long long)N_NODES));
        if (threadIdx.x == 0) s_is64 = m ? 0 : 1;
    }
    __syncthreads();
    return s_is64;
}

// ---------------- prep: detect + pack edges + degree hist + zero smalls -----
__global__ void prep_kernel(const void* ei) {
    int is64 = detect_is64(ei);
    if (blockIdx.x == 0) {
        for (int i = threadIdx.x; i < N_GRAPHS; i += 256) {
            g_gsum[i] = 0.f; g_gcnt[i] = 0.f;
        }
        if (threadIdx.x == 0) g_done = 0;
    }
    int e = blockIdx.x * 256 + threadIdx.x;
    if (e >= N_EDGES) return;
    int s, d;
    if (is64) {
        const long long* p = (const long long*)ei;
        s = (int)p[e]; d = (int)p[N_EDGES + e];
    } else {
        const int* p = (const int*)ei;
        s = p[e]; d = p[N_EDGES + e];
    }
    s = min(max(s, 0), N_NODES - 1);
    d = min(max(d, 0), N_NODES - 1);
    g_edge[e] = (unsigned long long)(unsigned)s |
                ((unsigned long long)(unsigned)d << 32);
    atomicAdd(&g_degi[d], 1);
}

// ---------------- tiled GEMM: 256-node x 32-out tile, 4n x 8o per thread ----
// LAYER 1: in = x (f32 global, K=128)      -> h1' = (in@W1)*dis fp16, zero agg1
// LAYER 2: in = relu(dis*(agg1+h1')+b1)    -> h2' = (in@W2)*dis fp16, zero agg2
template <int K, int LAYER>
__global__ __launch_bounds__(256) void gemm_tiled(const float* __restrict__ x,
                                                  const float* __restrict__ W,
                                                  const float* __restrict__ b1) {
    constexpr int KT = 32;
    constexpr int NPAD = 264;   // 264%32=8 -> conflict-free transpose stores
    __shared__ float Ws[K * 32];
    __shared__ float xs[KT * NPAD];

    int tid = threadIdx.x;
    for (int i = tid; i < K * 8; i += 256)
        ((float4*)Ws)[i] = ((const float4*)W)[i];

    int base = blockIdx.x * 256;
    int tx = tid & 3;          // out-group: outs [tx*8, tx*8+8)
    int ty = tid >> 2;         // node-group: nodes base+ty*4 .. +4

    unsigned long long acc[4][4];
#pragma unroll
    for (int i = 0; i < 4; i++)
#pragma unroll
        for (int q = 0; q < 4; q++) acc[i][q] = 0ULL;

    int mync = min(base + tid, N_NODES - 1);   // clamped staging node

#pragma unroll
    for (int kt = 0; kt < K / KT; kt++) {
        // ---- stage k-transposed input tile ----
        if (LAYER == 1) {
            const float4* row = (const float4*)(x + (size_t)mync * 128 + kt * KT);
#pragma unroll
            for (int j = 0; j < 8; j++) {
                float4 v = row[j];
                xs[(4 * j + 0) * NPAD + tid] = v.x;
                xs[(4 * j + 1) * NPAD + tid] = v.y;
                xs[(4 * j + 2) * NPAD + tid] = v.z;
                xs[(4 * j + 3) * NPAD + tid] = v.w;
            }
        } else {
            float dis = rsqrtf((float)g_degi[mync] + 1.0f);
            const uint2* aggp = g_agg1h + (size_t)mync * 8;
            const uint2* hp = g_h1h + (size_t)mync * 8;
#pragma unroll
            for (int cq = 0; cq < 8; cq++) {
                uint2 av = aggp[cq], hv = hp[cq];
                float2 a01 = u2f2(av.x), a23 = u2f2(av.y);
                float2 h01 = u2f2(hv.x), h23 = u2f2(hv.y);
                float4 b = ((const float4*)b1)[cq];
                xs[(4 * cq + 0) * NPAD + tid] = fmaxf(fmaf(dis, a01.x + h01.x, b.x), 0.f);
                xs[(4 * cq + 1) * NPAD + tid] = fmaxf(fmaf(dis, a01.y + h01.y, b.y), 0.f);
                xs[(4 * cq + 2) * NPAD + tid] = fmaxf(fmaf(dis, a23.x + h23.x, b.z), 0.f);
                xs[(4 * cq + 3) * NPAD + tid] = fmaxf(fmaf(dis, a23.y + h23.y, b.w), 0.f);
            }
        }
        __syncthreads();

        // ---- compute ----
#pragma unroll
        for (int k = 0; k < KT; k++) {
            float4 xv = *(const float4*)&xs[k * NPAD + ty * 4];
            const ulonglong2* wr = (const ulonglong2*)(Ws + (kt * KT + k) * 32 + tx * 8);
            ulonglong2 w0 = wr[0];
            ulonglong2 w1 = wr[1];
            unsigned long long xp0 = pack2(xv.x);
            unsigned long long xp1 = pack2(xv.y);
            unsigned long long xp2 = pack2(xv.z);
            unsigned long long xp3 = pack2(xv.w);
            ffma2(acc[0][0], xp0, w0.x); ffma2(acc[0][1], xp0, w0.y);
            ffma2(acc[0][2], xp0, w1.x); ffma2(acc[0][3], xp0, w1.y);
            ffma2(acc[1][0], xp1, w0.x); ffma2(acc[1][1], xp1, w0.y);
            ffma2(acc[1][2], xp1, w1.x); ffma2(acc[1][3], xp1, w1.y);
            ffma2(acc[2][0], xp2, w0.x); ffma2(acc[2][1], xp2, w0.y);
            ffma2(acc[2][2], xp2, w1.x); ffma2(acc[2][3], xp2, w1.y);
            ffma2(acc[3][0], xp3, w0.x); ffma2(acc[3][1], xp3, w0.y);
            ffma2(acc[3][2], xp3, w1.x); ffma2(acc[3][3], xp3, w1.y);
        }
        __syncthreads();
    }

    // ---- epilogue: scale by dis, convert fp16, write h + zero agg ----
    uint2* hout = (LAYER == 1) ? g_h1h : g_h2h;
    uint2* aggout = (LAYER == 1) ? g_agg1h : g_agg2h;
#pragma unroll
    for (int i = 0; i < 4; i++) {
        int node = base + ty * 4 + i;
        if (node >= N_NODES) break;
        float dis = rsqrtf((float)g_degi[node] + 1.0f);
        float2 p0 = unpack2(acc[i][0]);
        float2 p1 = unpack2(acc[i][1]);
        float2 p2 = unpack2(acc[i][2]);
        float2 p3 = unpack2(acc[i][3]);
        uint4 t;
        t.x = h2u(__floats2half2_rn(p0.x * dis, p0.y * dis));
        t.y = h2u(__floats2half2_rn(p1.x * dis, p1.y * dis));
        t.z = h2u(__floats2half2_rn(p2.x * dis, p2.y * dis));
        t.w = h2u(__floats2half2_rn(p3.x * dis, p3.y * dis));
        *(uint4*)(hout + (size_t)node * 8 + tx * 2) = t;
        uint4 z; z.x = 0u; z.y = 0u; z.z = 0u; z.w = 0u;
        *(uint4*)(aggout + (size_t)node * 8 + tx * 2) = z;
    }
}

// ---------------- edge scatter: agg[dst] += h'[src] (all fp16) ---------------
// 8 lanes per edge (8B each); 4 independent edges per thread for MLP=4
template <int LAYER>
__global__ __launch_bounds__(256) void scatter_kernel() {
    const uint2* h = (LAYER == 1) ? g_h1h : g_h2h;
    uint2* agg = (LAYER == 1) ? g_agg1h : g_agg2h;
    const int Q = N_EDGES / 4;

    int idx = blockIdx.x * 256 + threadIdx.x;
    int e0 = idx >> 3;
    if (e0 >= Q) return;
    int c = idx & 7;

    unsigned long long ed0 = g_edge[e0];
    unsigned long long ed1 = g_edge[e0 + Q];
    unsigned long long ed2 = g_edge[e0 + 2 * Q];
    unsigned long long ed3 = g_edge[e0 + 3 * Q];

    uint2 v0 = h[(size_t)(unsigned)(ed0 & 0xffffffffu) * 8 + c];
    uint2 v1 = h[(size_t)(unsigned)(ed1 & 0xffffffffu) * 8 + c];
    uint2 v2 = h[(size_t)(unsigned)(ed2 & 0xffffffffu) * 8 + c];
    uint2 v3 = h[(size_t)(unsigned)(ed3 & 0xffffffffu) * 8 + c];

#pragma unroll
    for (int j = 0; j < 4; j++) {
        unsigned long long ed = (j == 0) ? ed0 : (j == 1) ? ed1 : (j == 2) ? ed2 : ed3;
        uint2 v = (j == 0) ? v0 : (j == 1) ? v1 : (j == 2) ? v2 : v3;
        uint2* p = agg + (size_t)(unsigned)(ed >> 32) * 8 + c;
        asm volatile("red.global.add.noftz.v2.f16x2 [%0], {%1,%2};"
                     :: "l"(p), "r"(v.x), "r"(v.y)
                     : "memory");
    }
}

// ---------------- pool: relu2 + bias + dot(Wo) + segment sums + final -------
__global__ void pool_kernel(const void* ei, const void* batch,
                            const float* __restrict__ b2,
                            const float* __restrict__ Wo,
                            const float* __restrict__ bo,
                            float* __restrict__ out) {
    int is64 = detect_is64(ei);
    int n = blockIdx.x * 256 + threadIdx.x;
    if (n < N_NODES) {
        int g;
        if (is64) g = (int)((const long long*)batch)[n];
        else      g = ((const int*)batch)[n];
        g = min(max(g, 0), N_GRAPHS - 1);
        float dis = rsqrtf((float)g_degi[n] + 1.0f);
        const uint2* a2 = g_agg2h + (size_t)n * 8;
        const uint2* hh = g_h2h + (size_t)n * 8;
        float s = 0.f;
#pragma unroll
        for (int c = 0; c < 8; c++) {
            uint2 av = a2[c];
            uint2 hv = hh[c];
            float2 a01 = u2f2(av.x), a23 = u2f2(av.y);
            float2 h01 = u2f2(hv.x), h23 = u2f2(hv.y);
            float4 b = ((const float4*)b2)[c];
            float4 w = ((const float4*)Wo)[c];
            s += fmaxf(fmaf(dis, a01.x + h01.x, b.x), 0.f) * w.x;
            s += fmaxf(fmaf(dis, a01.y + h01.y, b.y), 0.f) * w.y;
            s += fmaxf(fmaf(dis, a23.x + h23.x, b.z), 0.f) * w.z;
            s += fmaxf(fmaf(dis, a23.y + h23.y, b.w), 0.f) * w.w;
        }
        atomicAdd(&g_gsum[g], s);
        atomicAdd(&g_gcnt[g], 1.0f);
    }

    // last-block finalize
    __threadfence();
    __syncthreads();
    __shared__ int s_last;
    if (threadIdx.x == 0) {
        int t = atomicAdd(&g_done, 1);
        s_last = (t == (int)gridDim.x - 1) ? 1 : 0;
    }
    __syncthreads();
    if (s_last) {
        float bias = bo[0];
        for (int i = threadIdx.x; i < N_GRAPHS; i += 256) {
            float sv = atomicAdd(&g_gsum[i], 0.0f);   // coherent read
            float cv = atomicAdd(&g_gcnt[i], 0.0f);
            out[i] = sv / fmaxf(cv, 1.0f) + bias;
        }
        __syncthreads();
        if (threadIdx.x == 0) g_done = 0;   // self-reset for graph replay
    }
}

// ---------------- launch ----------------------------------------------------
extern "C" void kernel_launch(void* const* d_in, const int* in_sizes, int n_in,
                              void* d_out, int out_size) {
    const float* x   = (const float*)d_in[0];
    const void*  ei  = d_in[1];
    const void*  bat = d_in[2];
    const float* W1  = (const float*)d_in[3];
    const float* b1  = (const float*)d_in[4];
    const float* W2  = (const float*)d_in[5];
    const float* b2  = (const float*)d_in[6];
    const float* Wo  = (const float*)d_in[7];
    const float* bo  = (const float*)d_in[8];
    float* out = (float*)d_out;

    void* p_degi = nullptr;
    cudaGetSymbolAddress(&p_degi, g_degi);
    cudaMemsetAsync(p_degi, 0, N_NODES * sizeof(int));

    prep_kernel<<<(N_EDGES + 255) / 256, 256>>>(ei);

    const int GB = (N_NODES + 255) / 256;   // 391

    // layer 1
    gemm_tiled<128, 1><<<GB, 256>>>(x, W1, b1);
    scatter_kernel<1><<<(N_EDGES / 4 * 8 + 255) / 256, 256>>>();

    // layer 2 (fuse1 folded into gemm2 staging)
    gemm_tiled<32, 2><<<GB, 256>>>(x, W2, b1);
    scatter_kernel<2><<<(N_EDGES / 4 * 8 + 255) / 256, 256>>>();

    // pooling + head (final fold via last-block)
    pool_kernel<<<(N_NODES + 255) / 256, 256>>>(ei, bat, b2, Wo, bo, out);
}